// round 14
// baseline (speedup 1.0000x reference)
#include <cuda_runtime.h>
#include <cuda_bf16.h>
#include <cstdint>

#define N_NODES 50000
#define N_EDGES 800000
#define F 256
#define F2 (F / 2)
#define NCHUNK 196   // ceil(50000/256)

// split point for spmm1/gemm2 pipelining (multiple of 128 and of 2)
#define H0_ROWS 24960
#define H0_BLKS (H0_ROWS / 128)            // 195
#define H1_BLKS ((N_NODES - H0_ROWS + 127) / 128)   // 196

// ---------------- scratch (static device globals; no runtime alloc) -------
__device__ __align__(16) unsigned g_buf16[(size_t)N_NODES * F2];  // bf16x2 msgs (RAW)
__device__ __align__(16) unsigned h_buf16[(size_t)N_NODES * F2];  // bf16x2 acts
__device__ __align__(16) unsigned Wb16a[F * F2];                  // bf16x2 W1
__device__ __align__(16) unsigned Wb16b[F * F2];                  // bf16x2 W2
__device__ int   g_counts[N_NODES];
__device__ int   g_rowstart[N_NODES + 1];
__device__ int   g_cursor[N_NODES];
__device__ float g_dinv[N_NODES];
__device__ int   g_blocksum[NCHUNK];
__device__ __align__(16) int2 g_srcw[N_EDGES];    // (src, dinv[src] bits)

// ---------------- bf16 helpers ---------------------------------------------
__device__ __forceinline__ unsigned pack_bf16(float a, float b) {
    __nv_bfloat162 t = __floats2bfloat162_rn(a, b);
    return *(unsigned*)&t;
}

__device__ __forceinline__ float2 unpack_bf16(unsigned v) {
    __nv_bfloat162 t = *(__nv_bfloat162*)&v;
    return __bfloat1622float2(t);
}

// ---------------- prelude: W1/W2 -> bf16 AND zero counts (one kernel) ------
__global__ void prelude_kernel(const float* __restrict__ W1,
                               const float* __restrict__ W2) {
    int b = blockIdx.x;
    int t = threadIdx.x;
    if (b < 32) {
        int i = b * 1024 + t;
        float2 v = *(const float2*)&W1[2 * i];
        Wb16a[i] = pack_bf16(v.x, v.y);
    } else if (b < 64) {
        int i = (b - 32) * 1024 + t;
        float2 v = *(const float2*)&W2[2 * i];
        Wb16b[i] = pack_bf16(v.x, v.y);
    } else {
        int i = (b - 64) * 1024 + t;
        if (i < N_NODES) g_counts[i] = 0;
    }
}

// ---------------- graph preprocessing -------------------------------------
__global__ void hist_kernel(const int* __restrict__ dstp) {
    int e = blockIdx.x * blockDim.x + threadIdx.x;
    if (e < N_EDGES) atomicAdd(&g_counts[dstp[e]], 1);
}

__global__ void scanA_kernel() {   // per-chunk sums
    __shared__ int ws[8];
    int b = blockIdx.x;
    int i = b * 256 + threadIdx.x;
    int v = (i < N_NODES) ? g_counts[i] : 0;
    #pragma unroll
    for (int o = 16; o; o >>= 1) v += __shfl_down_sync(0xffffffffu, v, o);
    if ((threadIdx.x & 31) == 0) ws[threadIdx.x >> 5] = v;
    __syncthreads();
    if (threadIdx.x < 8) {
        int s = ws[threadIdx.x];
        #pragma unroll
        for (int o = 4; o; o >>= 1) s += __shfl_down_sync(0xffu, s, o);
        if (threadIdx.x == 0) g_blocksum[b] = s;
    }
}

// merged scanB+scanC
__global__ void scanC2_kernel() {
    __shared__ int ws[8];
    __shared__ int soff;
    const int b = blockIdx.x;
    const int t = threadIdx.x;
    const int lane = t & 31, w = t >> 5;

    int v2 = (t < b) ? g_blocksum[t] : 0;
    #pragma unroll
    for (int o = 16; o; o >>= 1) v2 += __shfl_down_sync(0xffffffffu, v2, o);
    if (lane == 0) ws[w] = v2;
    __syncthreads();
    if (t < 8) {
        int s = ws[t];
        #pragma unroll
        for (int o = 4; o; o >>= 1) s += __shfl_down_sync(0xffu, s, o);
        if (t == 0) soff = s;
    }
    __syncthreads();
    const int chunkOff = soff;
    __syncthreads();

    int i = b * 256 + t;
    int v = (i < N_NODES) ? g_counts[i] : 0;
    int incl = v;
    #pragma unroll
    for (int o = 1; o < 32; o <<= 1) {
        int x = __shfl_up_sync(0xffffffffu, incl, o);
        if (lane >= o) incl += x;
    }
    if (lane == 31) ws[w] = incl;
    __syncthreads();
    if (w == 0 && lane < 8) {
        int s = ws[lane];
        #pragma unroll
        for (int o = 1; o < 8; o <<= 1) {
            int x = __shfl_up_sync(0xffu, s, o);
            if (lane >= o) s += x;
        }
        ws[lane] = s;
    }
    __syncthreads();
    int woff = (w > 0) ? ws[w - 1] : 0;
    if (i < N_NODES) {
        int rs = chunkOff + woff + incl - v;
        g_rowstart[i] = rs;
        g_cursor[i]   = rs;
        g_dinv[i]     = rsqrtf((float)(v + 1));   // +1 self-loop
    }
    if (b == 0 && t == 0) g_rowstart[N_NODES] = N_EDGES;
}

__global__ void scatter_kernel(const int* __restrict__ srcp,
                               const int* __restrict__ dstp) {
    int e = blockIdx.x * blockDim.x + threadIdx.x;
    if (e < N_EDGES) {
        int s = srcp[e];
        int d = dstp[e];
        int pos = atomicAdd(&g_cursor[d], 1);
        g_srcw[pos] = make_int2(s, __float_as_int(g_dinv[s]));
    }
}

// ---------------- mma/ldsm helpers -----------------------------------------
__device__ __forceinline__ void ldsm_x4(unsigned& r0, unsigned& r1,
                                        unsigned& r2, unsigned& r3,
                                        unsigned addr) {
    asm volatile("ldmatrix.sync.aligned.m8n8.x4.shared.b16 {%0,%1,%2,%3}, [%4];"
                 : "=r"(r0), "=r"(r1), "=r"(r2), "=r"(r3) : "r"(addr));
}

__device__ __forceinline__ void ldsm_x4_t(unsigned& r0, unsigned& r1,
                                          unsigned& r2, unsigned& r3,
                                          unsigned addr) {
    asm volatile("ldmatrix.sync.aligned.m8n8.x4.trans.shared.b16 {%0,%1,%2,%3}, [%4];"
                 : "=r"(r0), "=r"(r1), "=r"(r2), "=r"(r3) : "r"(addr));
}

__device__ __forceinline__ void mma_bf16(float* c, const unsigned* a,
                                         unsigned b0, unsigned b1) {
    asm volatile(
        "mma.sync.aligned.m16n8k16.row.col.f32.bf16.bf16.f32 "
        "{%0,%1,%2,%3}, {%4,%5,%6,%7}, {%8,%9}, {%0,%1,%2,%3};\n"
        : "+f"(c[0]), "+f"(c[1]), "+f"(c[2]), "+f"(c[3])
        : "r"(a[0]), "r"(a[1]), "r"(a[2]), "r"(a[3]), "r"(b0), "r"(b1));
}

// ---------------- GEMM (bf16 mma.sync, smem-resident, frag double-buffer) --
#define BM 128
#define BN 256
#define PITCH 264   // ushorts: 528B rows -> 33r mod 8 = r (conflict-free)
#define SMEM_A_WORDS (BM * PITCH)
#define SMEM_B_WORDS (F * PITCH)
#define SMEM_BYTES ((SMEM_A_WORDS + SMEM_B_WORDS) * 2)   // 202752 B

template <int LAYER>
__global__ __launch_bounds__(512) void gemm_bf16_kernel(
        const float* __restrict__ Ain, const unsigned* __restrict__ Wb,
        int rowBase0) {
    extern __shared__ __align__(16) unsigned short sm[];
    unsigned short* As = sm;                    // [128][PITCH]
    unsigned short* Bs = sm + SMEM_A_WORDS;     // [256][PITCH] (k-major)

    unsigned* __restrict__ C = g_buf16;

    const int tid   = threadIdx.x;
    const int lane  = tid & 31;
    const int warp  = tid >> 5;
    const int warpM = warp & 1;
    const int warpN = warp >> 1;
    const int rowBase = rowBase0 + blockIdx.x * BM;

    // ---- stage A (full 128x256) ----
    if (LAYER == 1) {
        #pragma unroll
        for (int it = 0; it < 16; ++it) {
            int fidx = it * 512 + tid;
            int m  = fidx >> 6;
            int fc = fidx & 63;
            int gr = rowBase + m;
            float4 v = make_float4(0.f, 0.f, 0.f, 0.f);
            if (gr < N_NODES) v = *(const float4*)&Ain[(size_t)gr * F + fc * 4];
            uint2 pv;
            pv.x = pack_bf16(v.x, v.y);
            pv.y = pack_bf16(v.z, v.w);
            *(uint2*)&As[m * PITCH + fc * 4] = pv;
        }
    } else {
        #pragma unroll
        for (int it = 0; it < 8; ++it) {
            int qidx = it * 512 + tid;
            int m  = qidx >> 5;
            int qc = qidx & 31;
            int gr = rowBase + m;
            uint4 v = make_uint4(0u, 0u, 0u, 0u);
            if (gr < N_NODES) v = *(const uint4*)&h_buf16[(size_t)gr * F2 + qc * 4];
            *(uint4*)&As[m * PITCH + qc * 8] = v;
        }
    }

    // ---- stage B (full 256x256, k-major rows) ----
    #pragma unroll
    for (int it = 0; it < 16; ++it) {
        int qidx = it * 512 + tid;
        int k  = qidx >> 5;
        int qc = qidx & 31;
        uint4 v = *(const uint4*)&Wb[(size_t)k * F2 + qc * 4];
        *(uint4*)&Bs[k * PITCH + qc * 8] = v;
    }
    __syncthreads();   // the ONLY barrier

    const unsigned asBase = (unsigned)__cvta_generic_to_shared(As);
    const unsigned bsBase = (unsigned)__cvta_generic_to_shared(Bs);
    const unsigned aOff =
        asBase + (unsigned)((warpM * 64 + (lane & 15)) * PITCH + (lane >> 4) * 8) * 2;
    const unsigned bOff =
        bsBase + (unsigned)((lane & 15) * PITCH + warpN * 32 + (lane >> 4) * 8) * 2;

    float acc[4][4][4];
    #pragma unroll
    for (int mi = 0; mi < 4; mi++)
        #pragma unroll
        for (int ni = 0; ni < 4; ni++)
            #pragma unroll
            for (int q = 0; q < 4; q++) acc[mi][ni][q] = 0.f;

    unsigned afr[2][4][4], bfr[2][2][4];

    #define LD_FRAGS(buf, kt)                                                   \
        do {                                                                    \
            const unsigned _ak = aOff + (unsigned)((kt) * 16) * 2;              \
            const unsigned _bk = bOff + (unsigned)((kt) * 16 * PITCH) * 2;      \
            _Pragma("unroll")                                                   \
            for (int mi = 0; mi < 4; mi++)                                      \
                ldsm_x4(afr[buf][mi][0], afr[buf][mi][1],                       \
                        afr[buf][mi][2], afr[buf][mi][3],                       \
                        _ak + (unsigned)(mi * 16 * PITCH) * 2);                 \
            _Pragma("unroll")                                                   \
            for (int nb = 0; nb < 2; nb++)                                      \
                ldsm_x4_t(bfr[buf][nb][0], bfr[buf][nb][1],                     \
                          bfr[buf][nb][2], bfr[buf][nb][3],                     \
                          _bk + (unsigned)(nb * 16) * 2);                       \
        } while (0)

    LD_FRAGS(0, 0);
    #pragma unroll
    for (int kt = 0; kt < F / 16; ++kt) {
        const int cur = kt & 1;
        if (kt < F / 16 - 1) LD_FRAGS(cur ^ 1, kt + 1);
        #pragma unroll
        for (int mi = 0; mi < 4; mi++)
            #pragma unroll
            for (int ni = 0; ni < 4; ni++)
                mma_bf16(acc[mi][ni], afr[cur][mi],
                         bfr[cur][ni >> 1][(ni & 1) * 2],
                         bfr[cur][ni >> 1][(ni & 1) * 2 + 1]);
    }
    #undef LD_FRAGS

    // ---- epilogue: store RAW bf16x2 (dinv applied in SpMM) ----
    const int g  = lane >> 2;
    const int tg = lane & 3;
    #pragma unroll
    for (int mi = 0; mi < 4; mi++) {
        int r0 = rowBase + warpM * 64 + mi * 16 + g;
        int r1 = r0 + 8;
        #pragma unroll
        for (int ni = 0; ni < 4; ni++) {
            int c = warpN * 32 + ni * 8 + 2 * tg;
            if (r0 < N_NODES)
                C[(size_t)r0 * F2 + (c >> 1)] =
                    pack_bf16(acc[mi][ni][0], acc[mi][ni][1]);
            if (r1 < N_NODES)
                C[(size_t)r1 * F2 + (c >> 1)] =
                    pack_bf16(acc[mi][ni][2], acc[mi][ni][3]);
        }
    }
}

// ---------------- SpMM: out[d] = dinv[d]*(Σ dinv[s]·g[s] + dinv[d]·g[d]) --
template <bool FINAL>
__global__ __launch_bounds__(128) void spmm_kernel(
        const float* __restrict__ bias,
        const float* __restrict__ xres,
        float* __restrict__ outp,
        int nodeBase) {
    const int d = nodeBase + blockIdx.x * 2 + (threadIdx.x >> 6);
    const int t = threadIdx.x & 63;
    const uint2* __restrict__ g2 = (const uint2*)g_buf16;
    const int2* __restrict__ sw = g_srcw;

    const int s = g_rowstart[d];
    const int e = g_rowstart[d + 1];
    const float dd = g_dinv[d];

    uint2 sv = g2[(size_t)d * 64 + t];
    float2 s0 = unpack_bf16(sv.x), s1 = unpack_bf16(sv.y);
    float4 acc = make_float4(dd * s0.x, dd * s0.y, dd * s1.x, dd * s1.y);

    int j = s;
    for (; j + 4 <= e; j += 4) {
        int2 p0 = sw[j + 0];
        int2 p1 = sw[j + 1];
        int2 p2 = sw[j + 2];
        int2 p3 = sw[j + 3];
        uint2 v0 = g2[(size_t)p0.x * 64 + t];
        uint2 v1 = g2[(size_t)p1.x * 64 + t];
        uint2 v2 = g2[(size_t)p2.x * 64 + t];
        uint2 v3 = g2[(size_t)p3.x * 64 + t];
        float w0 = __int_as_float(p0.y), w1 = __int_as_float(p1.y);
        float w2 = __int_as_float(p2.y), w3 = __int_as_float(p3.y);
        float2 a, b;
        a = unpack_bf16(v0.x); b = unpack_bf16(v0.y);
        acc.x = fmaf(w0, a.x, acc.x); acc.y = fmaf(w0, a.y, acc.y);
        acc.z = fmaf(w0, b.x, acc.z); acc.w = fmaf(w0, b.y, acc.w);
        a = unpack_bf16(v1.x); b = unpack_bf16(v1.y);
        acc.x = fmaf(w1, a.x, acc.x); acc.y = fmaf(w1, a.y, acc.y);
        acc.z = fmaf(w1, b.x, acc.z); acc.w = fmaf(w1, b.y, acc.w);
        a = unpack_bf16(v2.x); b = unpack_bf16(v2.y);
        acc.x = fmaf(w2, a.x, acc.x); acc.y = fmaf(w2, a.y, acc.y);
        acc.z = fmaf(w2, b.x, acc.z); acc.w = fmaf(w2, b.y, acc.w);
        a = unpack_bf16(v3.x); b = unpack_bf16(v3.y);
        acc.x = fmaf(w3, a.x, acc.x); acc.y = fmaf(w3, a.y, acc.y);
        acc.z = fmaf(w3, b.x, acc.z); acc.w = fmaf(w3, b.y, acc.w);
    }
    for (; j < e; ++j) {
        int2 p = sw[j];
        uint2 v = g2[(size_t)p.x * 64 + t];
        float w = __int_as_float(p.y);
        float2 a = unpack_bf16(v.x), b = unpack_bf16(v.y);
        acc.x = fmaf(w, a.x, acc.x); acc.y = fmaf(w, a.y, acc.y);
        acc.z = fmaf(w, b.x, acc.z); acc.w = fmaf(w, b.y, acc.w);
    }

    const float4 bv = ((const float4*)bias)[t];
    float r0 = fmaxf(dd * acc.x + bv.x, 0.f);
    float r1 = fmaxf(dd * acc.y + bv.y, 0.f);
    float r2 = fmaxf(dd * acc.z + bv.z, 0.f);
    float r3 = fmaxf(dd * acc.w + bv.w, 0.f);
    if (FINAL) {
        const float4 xr = ((const float4*)xres)[(size_t)d * 64 + t];
        float4 o;
        o.x = 0.5f * (xr.x + r0);
        o.y = 0.5f * (xr.y + r1);
        o.z = 0.5f * (xr.z + r2);
        o.w = 0.5f * (xr.w + r3);
        ((float4*)outp)[(size_t)d * 64 + t] = o;
    } else {
        uint2 hv;
        hv.x = pack_bf16(r0, r1);
        hv.y = pack_bf16(r2, r3);
        ((uint2*)h_buf16)[(size_t)d * 64 + t] = hv;
    }
}

// ---------------- launch ---------------------------------------------------
extern "C" void kernel_launch(void* const* d_in, const int* in_sizes, int n_in,
                              void* d_out, int out_size) {
    const float* x  = (const float*)d_in[0];
    const int*   ei = (const int*)d_in[1];
    const float* W1 = (const float*)d_in[2];
    const float* b1 = (const float*)d_in[3];
    const float* W2 = (const float*)d_in[4];
    const float* b2 = (const float*)d_in[5];
    float* out = (float*)d_out;

    const int* srcp = ei;             // edge_index[0]
    const int* dstp = ei + N_EDGES;   // edge_index[1]

    const int TB = 256;
    const int nblk = (N_NODES + BM - 1) / BM;   // 391

    unsigned *wa_ptr = nullptr, *wb_ptr = nullptr;
    cudaGetSymbolAddress((void**)&wa_ptr, Wb16a);
    cudaGetSymbolAddress((void**)&wb_ptr, Wb16b);

    cudaFuncSetAttribute(gemm_bf16_kernel<1>,
                         cudaFuncAttributeMaxDynamicSharedMemorySize, SMEM_BYTES);
    cudaFuncSetAttribute(gemm_bf16_kernel<2>,
                         cudaFuncAttributeMaxDynamicSharedMemorySize, SMEM_BYTES);

    cudaStream_t s2 = 0;
    cudaEvent_t eF = 0, eP = 0, eH0 = 0, eH1 = 0;
    bool forked =
        (cudaStreamCreateWithFlags(&s2, cudaStreamNonBlocking) == cudaSuccess) &&
        (cudaEventCreateWithFlags(&eF, cudaEventDisableTiming) == cudaSuccess) &&
        (cudaEventCreateWithFlags(&eP, cudaEventDisableTiming) == cudaSuccess) &&
        (cudaEventCreateWithFlags(&eH0, cudaEventDisableTiming) == cudaSuccess) &&
        (cudaEventCreateWithFlags(&eH1, cudaEventDisableTiming) == cudaSuccess);

    if (forked) {
        prelude_kernel<<<113, 1024>>>(W1, W2);
        cudaEventRecord(eF, 0);
        cudaStreamWaitEvent(s2, eF, 0);

        // gemm1 (main) || graph prep (s2)
        gemm_bf16_kernel<1><<<nblk, 512, SMEM_BYTES>>>(x, wa_ptr, 0);
        hist_kernel<<<(N_EDGES + TB - 1) / TB, TB, 0, s2>>>(dstp);
        scanA_kernel<<<NCHUNK, 256, 0, s2>>>();
        scanC2_kernel<<<NCHUNK, 256, 0, s2>>>();
        scatter_kernel<<<(N_EDGES + TB - 1) / TB, TB, 0, s2>>>(srcp, dstp);
        cudaEventRecord(eP, s2);
        cudaStreamWaitEvent(0, eP, 0);

        // spmm1_h0 (main), then gemm2_h0 (main) || spmm1_h1 (s2)
        spmm_kernel<false><<<H0_ROWS / 2, 128>>>(b1, nullptr, nullptr, 0);
        cudaEventRecord(eH0, 0);
        cudaStreamWaitEvent(s2, eH0, 0);
        spmm_kernel<false><<<(N_NODES - H0_ROWS) / 2, 128, 0, s2>>>(
            b1, nullptr, nullptr, H0_ROWS);
        gemm_bf16_kernel<2><<<H0_BLKS, 512, SMEM_BYTES>>>(nullptr, wb_ptr, 0);
        cudaEventRecord(eH1, s2);
        cudaStreamWaitEvent(0, eH1, 0);
        gemm_bf16_kernel<2><<<H1_BLKS, 512, SMEM_BYTES>>>(nullptr, wb_ptr, H0_ROWS);

        // final spmm (needs full g2)
        spmm_kernel<true><<<N_NODES / 2, 128>>>(b2, x, out, 0);
    } else {
        // serial fallback
        prelude_kernel<<<113, 1024>>>(W1, W2);
        hist_kernel<<<(N_EDGES + TB - 1) / TB, TB>>>(dstp);
        scanA_kernel<<<NCHUNK, 256>>>();
        scanC2_kernel<<<NCHUNK, 256>>>();
        scatter_kernel<<<(N_EDGES + TB - 1) / TB, TB>>>(srcp, dstp);
        gemm_bf16_kernel<1><<<nblk, 512, SMEM_BYTES>>>(x, wa_ptr, 0);
        spmm_kernel<false><<<N_NODES / 2, 128>>>(b1, nullptr, nullptr, 0);
        gemm_bf16_kernel<2><<<nblk, 512, SMEM_BYTES>>>(nullptr, wb_ptr, 0);
        spmm_kernel<true><<<N_NODES / 2, 128>>>(b2, x, out, 0);
    }
}

// round 15
// speedup vs baseline: 1.0840x; 1.0840x over previous
#include <cuda_runtime.h>
#include <cuda_bf16.h>
#include <cstdint>

#define N_NODES 50000
#define N_EDGES 800000
#define F 256
#define F2 (F / 2)
#define NCHUNK 196   // ceil(50000/256)

// ---------------- scratch (static device globals; no runtime alloc) -------
__device__ __align__(16) unsigned g_buf16[(size_t)N_NODES * F2];  // bf16x2 msgs (RAW)
__device__ __align__(16) unsigned h_buf16[(size_t)N_NODES * F2];  // bf16x2 acts
__device__ __align__(16) unsigned Wb16a[F * F2];                  // bf16x2 W1
__device__ __align__(16) unsigned Wb16b[F * F2];                  // bf16x2 W2
__device__ int   g_counts[N_NODES];
__device__ int   g_rowstart[N_NODES + 1];
__device__ int   g_cursor[N_NODES];
__device__ float g_dinv[N_NODES];
__device__ int   g_blocksum[NCHUNK];
__device__ __align__(16) int2 g_srcw[N_EDGES];    // (src, dinv[src] bits)

// ---------------- bf16 helpers ---------------------------------------------
__device__ __forceinline__ unsigned pack_bf16(float a, float b) {
    __nv_bfloat162 t = __floats2bfloat162_rn(a, b);
    return *(unsigned*)&t;
}

__device__ __forceinline__ float2 unpack_bf16(unsigned v) {
    __nv_bfloat162 t = *(__nv_bfloat162*)&v;
    return __bfloat1622float2(t);
}

// ---------------- prelude: W1/W2 -> bf16 AND zero counts (one kernel) ------
__global__ void prelude_kernel(const float* __restrict__ W1,
                               const float* __restrict__ W2) {
    int b = blockIdx.x;
    int t = threadIdx.x;
    if (b < 32) {
        int i = b * 1024 + t;
        float2 v = *(const float2*)&W1[2 * i];
        Wb16a[i] = pack_bf16(v.x, v.y);
    } else if (b < 64) {
        int i = (b - 32) * 1024 + t;
        float2 v = *(const float2*)&W2[2 * i];
        Wb16b[i] = pack_bf16(v.x, v.y);
    } else {
        int i = (b - 64) * 1024 + t;
        if (i < N_NODES) g_counts[i] = 0;
    }
}

// ---------------- graph preprocessing -------------------------------------
__global__ void hist_kernel(const int* __restrict__ dstp) {
    int e = blockIdx.x * blockDim.x + threadIdx.x;
    if (e < N_EDGES) atomicAdd(&g_counts[dstp[e]], 1);
}

__global__ void scanA_kernel() {   // per-chunk sums
    __shared__ int ws[8];
    int b = blockIdx.x;
    int i = b * 256 + threadIdx.x;
    int v = (i < N_NODES) ? g_counts[i] : 0;
    #pragma unroll
    for (int o = 16; o; o >>= 1) v += __shfl_down_sync(0xffffffffu, v, o);
    if ((threadIdx.x & 31) == 0) ws[threadIdx.x >> 5] = v;
    __syncthreads();
    if (threadIdx.x < 8) {
        int s = ws[threadIdx.x];
        #pragma unroll
        for (int o = 4; o; o >>= 1) s += __shfl_down_sync(0xffu, s, o);
        if (threadIdx.x == 0) g_blocksum[b] = s;
    }
}

// merged scanB+scanC
__global__ void scanC2_kernel() {
    __shared__ int ws[8];
    __shared__ int soff;
    const int b = blockIdx.x;
    const int t = threadIdx.x;
    const int lane = t & 31, w = t >> 5;

    int v2 = (t < b) ? g_blocksum[t] : 0;
    #pragma unroll
    for (int o = 16; o; o >>= 1) v2 += __shfl_down_sync(0xffffffffu, v2, o);
    if (lane == 0) ws[w] = v2;
    __syncthreads();
    if (t < 8) {
        int s = ws[t];
        #pragma unroll
        for (int o = 4; o; o >>= 1) s += __shfl_down_sync(0xffu, s, o);
        if (t == 0) soff = s;
    }
    __syncthreads();
    const int chunkOff = soff;
    __syncthreads();

    int i = b * 256 + t;
    int v = (i < N_NODES) ? g_counts[i] : 0;
    int incl = v;
    #pragma unroll
    for (int o = 1; o < 32; o <<= 1) {
        int x = __shfl_up_sync(0xffffffffu, incl, o);
        if (lane >= o) incl += x;
    }
    if (lane == 31) ws[w] = incl;
    __syncthreads();
    if (w == 0 && lane < 8) {
        int s = ws[lane];
        #pragma unroll
        for (int o = 1; o < 8; o <<= 1) {
            int x = __shfl_up_sync(0xffu, s, o);
            if (lane >= o) s += x;
        }
        ws[lane] = s;
    }
    __syncthreads();
    int woff = (w > 0) ? ws[w - 1] : 0;
    if (i < N_NODES) {
        int rs = chunkOff + woff + incl - v;
        g_rowstart[i] = rs;
        g_cursor[i]   = rs;
        g_dinv[i]     = rsqrtf((float)(v + 1));   // +1 self-loop
    }
    if (b == 0 && t == 0) g_rowstart[N_NODES] = N_EDGES;
}

__global__ void scatter_kernel(const int* __restrict__ srcp,
                               const int* __restrict__ dstp) {
    int e = blockIdx.x * blockDim.x + threadIdx.x;
    if (e < N_EDGES) {
        int s = srcp[e];
        int d = dstp[e];
        int pos = atomicAdd(&g_cursor[d], 1);
        g_srcw[pos] = make_int2(s, __float_as_int(g_dinv[s]));
    }
}

// ---------------- mma/ldsm helpers -----------------------------------------
__device__ __forceinline__ void ldsm_x4(unsigned& r0, unsigned& r1,
                                        unsigned& r2, unsigned& r3,
                                        unsigned addr) {
    asm volatile("ldmatrix.sync.aligned.m8n8.x4.shared.b16 {%0,%1,%2,%3}, [%4];"
                 : "=r"(r0), "=r"(r1), "=r"(r2), "=r"(r3) : "r"(addr));
}

__device__ __forceinline__ void ldsm_x4_t(unsigned& r0, unsigned& r1,
                                          unsigned& r2, unsigned& r3,
                                          unsigned addr) {
    asm volatile("ldmatrix.sync.aligned.m8n8.x4.trans.shared.b16 {%0,%1,%2,%3}, [%4];"
                 : "=r"(r0), "=r"(r1), "=r"(r2), "=r"(r3) : "r"(addr));
}

__device__ __forceinline__ void mma_bf16(float* c, const unsigned* a,
                                         unsigned b0, unsigned b1) {
    asm volatile(
        "mma.sync.aligned.m16n8k16.row.col.f32.bf16.bf16.f32 "
        "{%0,%1,%2,%3}, {%4,%5,%6,%7}, {%8,%9}, {%0,%1,%2,%3};\n"
        : "+f"(c[0]), "+f"(c[1]), "+f"(c[2]), "+f"(c[3])
        : "r"(a[0]), "r"(a[1]), "r"(a[2]), "r"(a[3]), "r"(b0), "r"(b1));
}

// ---------------- GEMM (bf16 mma.sync, smem-resident, 8 warps 64x64 tiles) -
// M=50000, N=K=256. CTA: 128x256, 256 threads, 8 warps 2(M)x4(N), warp 64x64.
// Fragment redundancy: A 4x + B 2x = 512KB smem reads per CTA (was 768KB).
#define BM 128
#define BN 256
#define PITCH 264   // ushorts: 528B rows -> 33r mod 8 = r (conflict-free)
#define SMEM_A_WORDS (BM * PITCH)
#define SMEM_B_WORDS (F * PITCH)
#define SMEM_BYTES ((SMEM_A_WORDS + SMEM_B_WORDS) * 2)   // 202752 B

template <int LAYER>
__global__ __launch_bounds__(256) void gemm_bf16_kernel(
        const float* __restrict__ Ain, const unsigned* __restrict__ Wb) {
    extern __shared__ __align__(16) unsigned short sm[];
    unsigned short* As = sm;                    // [128][PITCH]
    unsigned short* Bs = sm + SMEM_A_WORDS;     // [256][PITCH] (k-major)

    unsigned* __restrict__ C = g_buf16;

    const int tid   = threadIdx.x;
    const int lane  = tid & 31;
    const int warp  = tid >> 5;                 // 0..7
    const int warpM = warp & 1;                 // 64-row slab
    const int warpN = warp >> 1;                // 0..3 -> 64-col slab
    const int rowBase = blockIdx.x * BM;

    // ---- stage A (full 128x256) ----
    if (LAYER == 1) {
        #pragma unroll
        for (int it = 0; it < 32; ++it) {
            int fidx = it * 256 + tid;          // 0..8191
            int m  = fidx >> 6;
            int fc = fidx & 63;
            int gr = rowBase + m;
            float4 v = make_float4(0.f, 0.f, 0.f, 0.f);
            if (gr < N_NODES) v = *(const float4*)&Ain[(size_t)gr * F + fc * 4];
            uint2 pv;
            pv.x = pack_bf16(v.x, v.y);
            pv.y = pack_bf16(v.z, v.w);
            *(uint2*)&As[m * PITCH + fc * 4] = pv;
        }
    } else {
        #pragma unroll
        for (int it = 0; it < 16; ++it) {
            int qidx = it * 256 + tid;          // 0..4095
            int m  = qidx >> 5;
            int qc = qidx & 31;
            int gr = rowBase + m;
            uint4 v = make_uint4(0u, 0u, 0u, 0u);
            if (gr < N_NODES) v = *(const uint4*)&h_buf16[(size_t)gr * F2 + qc * 4];
            *(uint4*)&As[m * PITCH + qc * 8] = v;
        }
    }

    // ---- stage B (full 256x256, k-major rows) ----
    #pragma unroll
    for (int it = 0; it < 32; ++it) {
        int qidx = it * 256 + tid;              // 0..8191
        int k  = qidx >> 5;
        int qc = qidx & 31;
        uint4 v = *(const uint4*)&Wb[(size_t)k * F2 + qc * 4];
        *(uint4*)&Bs[k * PITCH + qc * 8] = v;
    }
    __syncthreads();   // the ONLY barrier

    const unsigned asBase = (unsigned)__cvta_generic_to_shared(As);
    const unsigned bsBase = (unsigned)__cvta_generic_to_shared(Bs);
    const unsigned aOff =
        asBase + (unsigned)((warpM * 64 + (lane & 15)) * PITCH + (lane >> 4) * 8) * 2;
    const unsigned bOff =
        bsBase + (unsigned)((lane & 15) * PITCH + warpN * 64 + (lane >> 4) * 8) * 2;

    float acc[4][8][4];
    #pragma unroll
    for (int mi = 0; mi < 4; mi++)
        #pragma unroll
        for (int ni = 0; ni < 8; ni++)
            #pragma unroll
            for (int q = 0; q < 4; q++) acc[mi][ni][q] = 0.f;

    #pragma unroll
    for (int kt = 0; kt < F / 16; ++kt) {
        unsigned afr[4][4], bfr[4][4];
        const unsigned ak = aOff + (unsigned)(kt * 16) * 2;           // k cols
        const unsigned bk = bOff + (unsigned)(kt * 16 * PITCH) * 2;   // k rows
        #pragma unroll
        for (int mi = 0; mi < 4; mi++)
            ldsm_x4(afr[mi][0], afr[mi][1], afr[mi][2], afr[mi][3],
                    ak + (unsigned)(mi * 16 * PITCH) * 2);
        #pragma unroll
        for (int nb = 0; nb < 4; nb++)
            ldsm_x4_t(bfr[nb][0], bfr[nb][1], bfr[nb][2], bfr[nb][3],
                      bk + (unsigned)(nb * 16) * 2);
        #pragma unroll
        for (int mi = 0; mi < 4; mi++)
            #pragma unroll
            for (int ni = 0; ni < 8; ni++)
                mma_bf16(acc[mi][ni], afr[mi],
                         bfr[ni >> 1][(ni & 1) * 2], bfr[ni >> 1][(ni & 1) * 2 + 1]);
    }

    // ---- epilogue: store RAW bf16x2 (dinv applied in SpMM) ----
    const int g  = lane >> 2;
    const int tg = lane & 3;
    #pragma unroll
    for (int mi = 0; mi < 4; mi++) {
        int r0 = rowBase + warpM * 64 + mi * 16 + g;
        int r1 = r0 + 8;
        #pragma unroll
        for (int ni = 0; ni < 8; ni++) {
            int c = warpN * 64 + ni * 8 + 2 * tg;
            if (r0 < N_NODES)
                C[(size_t)r0 * F2 + (c >> 1)] =
                    pack_bf16(acc[mi][ni][0], acc[mi][ni][1]);
            if (r1 < N_NODES)
                C[(size_t)r1 * F2 + (c >> 1)] =
                    pack_bf16(acc[mi][ni][2], acc[mi][ni][3]);
        }
    }
}

// ---------------- SpMM: out[d] = dinv[d]*(Σ dinv[s]·g[s] + dinv[d]·g[d]) --
template <bool FINAL>
__global__ __launch_bounds__(128) void spmm_kernel(
        const float* __restrict__ bias,
        const float* __restrict__ xres,
        float* __restrict__ outp) {
    const int d = blockIdx.x * 2 + (threadIdx.x >> 6);
    const int t = threadIdx.x & 63;
    const uint2* __restrict__ g2 = (const uint2*)g_buf16;
    const int2* __restrict__ sw = g_srcw;

    const int s = g_rowstart[d];
    const int e = g_rowstart[d + 1];
    const float dd = g_dinv[d];

    uint2 sv = g2[(size_t)d * 64 + t];
    float2 s0 = unpack_bf16(sv.x), s1 = unpack_bf16(sv.y);
    float4 acc = make_float4(dd * s0.x, dd * s0.y, dd * s1.x, dd * s1.y);

    int j = s;
    for (; j + 4 <= e; j += 4) {
        int2 p0 = sw[j + 0];
        int2 p1 = sw[j + 1];
        int2 p2 = sw[j + 2];
        int2 p3 = sw[j + 3];
        uint2 v0 = g2[(size_t)p0.x * 64 + t];
        uint2 v1 = g2[(size_t)p1.x * 64 + t];
        uint2 v2 = g2[(size_t)p2.x * 64 + t];
        uint2 v3 = g2[(size_t)p3.x * 64 + t];
        float w0 = __int_as_float(p0.y), w1 = __int_as_float(p1.y);
        float w2 = __int_as_float(p2.y), w3 = __int_as_float(p3.y);
        float2 a, b;
        a = unpack_bf16(v0.x); b = unpack_bf16(v0.y);
        acc.x = fmaf(w0, a.x, acc.x); acc.y = fmaf(w0, a.y, acc.y);
        acc.z = fmaf(w0, b.x, acc.z); acc.w = fmaf(w0, b.y, acc.w);
        a = unpack_bf16(v1.x); b = unpack_bf16(v1.y);
        acc.x = fmaf(w1, a.x, acc.x); acc.y = fmaf(w1, a.y, acc.y);
        acc.z = fmaf(w1, b.x, acc.z); acc.w = fmaf(w1, b.y, acc.w);
        a = unpack_bf16(v2.x); b = unpack_bf16(v2.y);
        acc.x = fmaf(w2, a.x, acc.x); acc.y = fmaf(w2, a.y, acc.y);
        acc.z = fmaf(w2, b.x, acc.z); acc.w = fmaf(w2, b.y, acc.w);
        a = unpack_bf16(v3.x); b = unpack_bf16(v3.y);
        acc.x = fmaf(w3, a.x, acc.x); acc.y = fmaf(w3, a.y, acc.y);
        acc.z = fmaf(w3, b.x, acc.z); acc.w = fmaf(w3, b.y, acc.w);
    }
    for (; j < e; ++j) {
        int2 p = sw[j];
        uint2 v = g2[(size_t)p.x * 64 + t];
        float w = __int_as_float(p.y);
        float2 a = unpack_bf16(v.x), b = unpack_bf16(v.y);
        acc.x = fmaf(w, a.x, acc.x); acc.y = fmaf(w, a.y, acc.y);
        acc.z = fmaf(w, b.x, acc.z); acc.w = fmaf(w, b.y, acc.w);
    }

    const float4 bv = ((const float4*)bias)[t];
    float r0 = fmaxf(dd * acc.x + bv.x, 0.f);
    float r1 = fmaxf(dd * acc.y + bv.y, 0.f);
    float r2 = fmaxf(dd * acc.z + bv.z, 0.f);
    float r3 = fmaxf(dd * acc.w + bv.w, 0.f);
    if (FINAL) {
        const float4 xr = ((const float4*)xres)[(size_t)d * 64 + t];
        float4 o;
        o.x = 0.5f * (xr.x + r0);
        o.y = 0.5f * (xr.y + r1);
        o.z = 0.5f * (xr.z + r2);
        o.w = 0.5f * (xr.w + r3);
        ((float4*)outp)[(size_t)d * 64 + t] = o;
    } else {
        uint2 hv;
        hv.x = pack_bf16(r0, r1);
        hv.y = pack_bf16(r2, r3);
        ((uint2*)h_buf16)[(size_t)d * 64 + t] = hv;
    }
}

// ---------------- launch ---------------------------------------------------
extern "C" void kernel_launch(void* const* d_in, const int* in_sizes, int n_in,
                              void* d_out, int out_size) {
    const float* x  = (const float*)d_in[0];
    const int*   ei = (const int*)d_in[1];
    const float* W1 = (const float*)d_in[2];
    const float* b1 = (const float*)d_in[3];
    const float* W2 = (const float*)d_in[4];
    const float* b2 = (const float*)d_in[5];
    float* out = (float*)d_out;

    const int* srcp = ei;             // edge_index[0]
    const int* dstp = ei + N_EDGES;   // edge_index[1]

    const int TB = 256;
    const int nblk = (N_NODES + BM - 1) / BM;   // 391

    unsigned *wa_ptr = nullptr, *wb_ptr = nullptr;
    cudaGetSymbolAddress((void**)&wa_ptr, Wb16a);
    cudaGetSymbolAddress((void**)&wb_ptr, Wb16b);

    cudaFuncSetAttribute(gemm_bf16_kernel<1>,
                         cudaFuncAttributeMaxDynamicSharedMemorySize, SMEM_BYTES);
    cudaFuncSetAttribute(gemm_bf16_kernel<2>,
                         cudaFuncAttributeMaxDynamicSharedMemorySize, SMEM_BYTES);

    cudaStream_t s2 = 0;
    cudaEvent_t eF = 0, eP = 0;
    bool forked =
        (cudaStreamCreateWithFlags(&s2, cudaStreamNonBlocking) == cudaSuccess) &&
        (cudaEventCreateWithFlags(&eF, cudaEventDisableTiming) == cudaSuccess) &&
        (cudaEventCreateWithFlags(&eP, cudaEventDisableTiming) == cudaSuccess);

    if (forked) {
        prelude_kernel<<<113, 1024>>>(W1, W2);
        cudaEventRecord(eF, 0);
        cudaStreamWaitEvent(s2, eF, 0);

        // gemm1 (main) || graph prep (s2)
        gemm_bf16_kernel<1><<<nblk, 256, SMEM_BYTES>>>(x, wa_ptr);
        hist_kernel<<<(N_EDGES + TB - 1) / TB, TB, 0, s2>>>(dstp);
        scanA_kernel<<<NCHUNK, 256, 0, s2>>>();
        scanC2_kernel<<<NCHUNK, 256, 0, s2>>>();
        scatter_kernel<<<(N_EDGES + TB - 1) / TB, TB, 0, s2>>>(srcp, dstp);

        cudaEventRecord(eP, s2);
        cudaStreamWaitEvent(0, eP, 0);
        spmm_kernel<false><<<N_NODES / 2, 128>>>(b1, nullptr, nullptr);
        gemm_bf16_kernel<2><<<nblk, 256, SMEM_BYTES>>>(nullptr, wb_ptr);
        spmm_kernel<true><<<N_NODES / 2, 128>>>(b2, x, out);
    } else {
        // serial fallback
        prelude_kernel<<<113, 1024>>>(W1, W2);
        hist_kernel<<<(N_EDGES + TB - 1) / TB, TB>>>(dstp);
        scanA_kernel<<<NCHUNK, 256>>>();
        scanC2_kernel<<<NCHUNK, 256>>>();
        scatter_kernel<<<(N_EDGES + TB - 1) / TB, TB>>>(srcp, dstp);
        gemm_bf16_kernel<1><<<nblk, 256, SMEM_BYTES>>>(x, wa_ptr);
        spmm_kernel<false><<<N_NODES / 2, 128>>>(b1, nullptr, nullptr);
        gemm_bf16_kernel<2><<<nblk, 256, SMEM_BYTES>>>(nullptr, wb_ptr);
        spmm_kernel<true><<<N_NODES / 2, 128>>>(b2, x, out);
    }
}